// round 4
// baseline (speedup 1.0000x reference)
#include <cuda_runtime.h>
#include <cuda_bf16.h>
#include <math_constants.h>
#include <cstdint>

// Problem constants
#define N_NODES 20000
#define N_PAD   20096          // 157 * 128
#define IN_CH   512
#define HC      512
#define HEADS   8
#define CH      64
#define E_EDGES 320000
#define E_LABEL 100000
#define BN_BLOCKS 128

// ---------------- scratch ----------------
__device__ __nv_bfloat16 g_xhi[N_PAD * IN_CH];
__device__ __nv_bfloat16 g_xlo[N_PAD * IN_CH];
__device__ __nv_bfloat16 g_wthi[2][IN_CH * HC];
__device__ __nv_bfloat16 g_wtlo[2][IN_CH * HC];
__device__ float g_xl[N_PAD * HC];
__device__ float g_xr[N_PAD * HC];
__device__ float g_out[N_NODES * HC];
__device__ int   g_deg[N_NODES + 1];
__device__ int   g_off[N_NODES + 1];
__device__ int   g_cur[N_NODES];
__device__ int   g_csr_src[E_EDGES];
__device__ int   g_bsum[32];
__device__ int   g_boff[32];
__device__ float g_psum[BN_BLOCKS * HC];
__device__ float g_psq [BN_BLOCKS * HC];
__device__ float g_scale[HC];
__device__ float g_shift[HC];

// ---------------- helpers ----------------
__device__ __forceinline__ uint32_t smem_u32(const void* p) {
    uint32_t a;
    asm("{ .reg .u64 t; cvta.to.shared.u64 t, %1; cvt.u32.u64 %0, t; }" : "=r"(a) : "l"(p));
    return a;
}
__device__ __forceinline__ void cp_async16(uint32_t sa, const void* ga) {
    asm volatile("cp.async.cg.shared.global [%0], [%1], 16;" :: "r"(sa), "l"(ga) : "memory");
}
__device__ __forceinline__ void cp_commit() {
    asm volatile("cp.async.commit_group;" ::: "memory");
}
__device__ __forceinline__ void cp_wait1() {
    asm volatile("cp.async.wait_group 1;" ::: "memory");
}
__device__ __forceinline__ void cp_wait0() {
    asm volatile("cp.async.wait_group 0;" ::: "memory");
}
__device__ __forceinline__ void ldm_x4(uint32_t* r, uint32_t addr) {
    asm volatile("ldmatrix.sync.aligned.m8n8.x4.shared.b16 {%0,%1,%2,%3}, [%4];"
                 : "=r"(r[0]), "=r"(r[1]), "=r"(r[2]), "=r"(r[3]) : "r"(addr));
}
__device__ __forceinline__ void mma16816(float* d, const uint32_t* a, const uint32_t* b) {
    asm volatile("mma.sync.aligned.m16n8k16.row.col.f32.bf16.bf16.f32 "
                 "{%0,%1,%2,%3}, {%4,%5,%6,%7}, {%8,%9}, {%0,%1,%2,%3};"
                 : "+f"(d[0]), "+f"(d[1]), "+f"(d[2]), "+f"(d[3])
                 : "r"(a[0]), "r"(a[1]), "r"(a[2]), "r"(a[3]), "r"(b[0]), "r"(b[1]));
}

// ---------------- bf16 split conversion ----------------
__global__ void conv_x_kernel(const float* __restrict__ x)
{
    int i4 = blockIdx.x * blockDim.x + threadIdx.x;
    if (i4 >= N_PAD * IN_CH / 4) return;
    int i = i4 * 4;
    int row = i >> 9;
    float4 v = (row < N_NODES) ? *(const float4*)(x + i) : make_float4(0.f, 0.f, 0.f, 0.f);
    float a[4] = {v.x, v.y, v.z, v.w};
    __nv_bfloat16 h0 = __float2bfloat16(a[0]);
    __nv_bfloat16 h1 = __float2bfloat16(a[1]);
    __nv_bfloat16 h2 = __float2bfloat16(a[2]);
    __nv_bfloat16 h3 = __float2bfloat16(a[3]);
    __nv_bfloat16 l0 = __float2bfloat16(a[0] - __bfloat162float(h0));
    __nv_bfloat16 l1 = __float2bfloat16(a[1] - __bfloat162float(h1));
    __nv_bfloat16 l2 = __float2bfloat16(a[2] - __bfloat162float(h2));
    __nv_bfloat16 l3 = __float2bfloat16(a[3] - __bfloat162float(h3));
    uint32_t hi01 = ((uint32_t)__bfloat16_as_ushort(h1) << 16) | __bfloat16_as_ushort(h0);
    uint32_t hi23 = ((uint32_t)__bfloat16_as_ushort(h3) << 16) | __bfloat16_as_ushort(h2);
    uint32_t lo01 = ((uint32_t)__bfloat16_as_ushort(l1) << 16) | __bfloat16_as_ushort(l0);
    uint32_t lo23 = ((uint32_t)__bfloat16_as_ushort(l3) << 16) | __bfloat16_as_ushort(l2);
    *(uint2*)((char*)g_xhi + i * 2) = make_uint2(hi01, hi23);
    *(uint2*)((char*)g_xlo + i * 2) = make_uint2(lo01, lo23);
}

// also zeroes g_deg (grid is large enough; runs before hist on the side stream)
__global__ void conv_w_kernel(const float* __restrict__ Wl, const float* __restrict__ Wr)
{
    int i = blockIdx.x * blockDim.x + threadIdx.x;   // n*512 + k
    int mat = blockIdx.y;
    if (mat == 0) {
        if (i <= N_NODES) g_deg[i] = 0;
    }
    const float* W = mat ? Wr : Wl;
    int n = i >> 9, k = i & 511;
    float v = W[k * HC + n];
    __nv_bfloat16 h = __float2bfloat16(v);
    g_wthi[mat][i] = h;
    g_wtlo[mat][i] = __float2bfloat16(v - __bfloat162float(h));
}

// ---------------- HMMA split-bf16 GEMM (3-stage cp.async ring) ----------------
#define SMS 80                      // smem row stride bytes (64B row + 16B pad)
#define TILE_BYTES (128 * SMS)      // 10240
#define NCHUNK 48                   // 3 passes * 16 k-chunks of 32

__global__ void __launch_bounds__(256, 2) gemm_tc_kernel()
{
    __shared__ __align__(16) char sA[3][TILE_BYTES];
    __shared__ __align__(16) char sB[3][TILE_BYTES];

    const int tid  = threadIdx.x;
    const int wid  = tid >> 5;
    const int lane = tid & 31;
    const int wm   = wid & 1;
    const int wn   = wid >> 1;

    const int m0  = blockIdx.y * 128;
    const int n0  = blockIdx.x * 128;
    const int mat = blockIdx.z;

    const __nv_bfloat16* Apass[3] = {g_xhi + (size_t)m0 * IN_CH,
                                     g_xhi + (size_t)m0 * IN_CH,
                                     g_xlo + (size_t)m0 * IN_CH};
    const __nv_bfloat16* Bpass[3] = {g_wthi[mat] + (size_t)n0 * IN_CH,
                                     g_wtlo[mat] + (size_t)n0 * IN_CH,
                                     g_wthi[mat] + (size_t)n0 * IN_CH};
    float* C = mat ? g_xr : g_xl;

    const uint32_t sAb[3] = {smem_u32(sA[0]), smem_u32(sA[1]), smem_u32(sA[2])};
    const uint32_t sBb[3] = {smem_u32(sB[0]), smem_u32(sB[1]), smem_u32(sB[2])};

    const int r0 = tid >> 2;
    const int c0 = tid & 3;

    float acc[4][4][4];
#pragma unroll
    for (int i = 0; i < 4; i++)
#pragma unroll
        for (int j = 0; j < 4; j++)
#pragma unroll
            for (int q = 0; q < 4; q++) acc[i][j][q] = 0.f;

    auto issue = [&](int c, int buf) {
        int pass = c >> 4;
        int kc   = c & 15;
        const __nv_bfloat16* Ag = Apass[pass];
        const __nv_bfloat16* Bg = Bpass[pass];
#pragma unroll
        for (int j = 0; j < 2; j++) {
            int row = r0 + j * 64;
            int kel = kc * 32 + c0 * 8;
            cp_async16(sAb[buf] + row * SMS + c0 * 16, Ag + (size_t)row * IN_CH + kel);
            cp_async16(sBb[buf] + row * SMS + c0 * 16, Bg + (size_t)row * IN_CH + kel);
        }
    };

    issue(0, 0); cp_commit();
    issue(1, 1); cp_commit();

    for (int c = 0; c < NCHUNK; c++) {
        if (c < NCHUNK - 1) cp_wait1(); else cp_wait0();
        __syncthreads();                       // chunk c visible; all done computing c-1
        if (c + 2 < NCHUNK) { issue(c + 2, (c + 2) % 3); cp_commit(); }

        const int buf = c % 3;
        const uint32_t a_base = sAb[buf];
        const uint32_t b_base = sBb[buf];
#pragma unroll
        for (int ks = 0; ks < 2; ks++) {
            const int kb = ks * 32;
            uint32_t a[4][4];
#pragma unroll
            for (int mt = 0; mt < 4; mt++) {
                int row = wm * 64 + mt * 16 + ((lane >> 3) & 1) * 8 + (lane & 7);
                uint32_t addr = a_base + row * SMS + kb + ((lane >> 4) & 1) * 16;
                ldm_x4(a[mt], addr);
            }
            uint32_t b[4][2];
#pragma unroll
            for (int nh = 0; nh < 2; nh++) {
                int row = wn * 32 + nh * 16 + (lane >> 4) * 8 + (lane & 7);
                uint32_t addr = b_base + row * SMS + kb + ((lane >> 3) & 1) * 16;
                uint32_t t[4];
                ldm_x4(t, addr);
                b[nh * 2 + 0][0] = t[0]; b[nh * 2 + 0][1] = t[1];
                b[nh * 2 + 1][0] = t[2]; b[nh * 2 + 1][1] = t[3];
            }
#pragma unroll
            for (int mt = 0; mt < 4; mt++)
#pragma unroll
                for (int nt = 0; nt < 4; nt++)
                    mma16816(acc[mt][nt], a[mt], b[nt]);
        }
    }

    const int g = lane >> 2;
    const int q = lane & 3;
#pragma unroll
    for (int mt = 0; mt < 4; mt++) {
#pragma unroll
        for (int nt = 0; nt < 4; nt++) {
            int row = m0 + wm * 64 + mt * 16 + g;
            int col = n0 + wn * 32 + nt * 8 + q * 2;
            *(float2*)&C[(size_t)row * HC + col] =
                make_float2(acc[mt][nt][0], acc[mt][nt][1]);
            *(float2*)&C[(size_t)(row + 8) * HC + col] =
                make_float2(acc[mt][nt][2], acc[mt][nt][3]);
        }
    }
}

// ---------------- CSR build ----------------
__global__ void hist_kernel(const int* __restrict__ ei)
{
    int e = blockIdx.x * blockDim.x + threadIdx.x;
    if (e < E_EDGES) atomicAdd(&g_deg[ei[E_EDGES + e]], 1);
}

__global__ void scan_blocks_kernel()     // 20 blocks x 1024
{
    __shared__ int wsum[32];
    int b = blockIdx.x, t = threadIdx.x;
    int i = b * 1024 + t;
    int v = (i < N_NODES) ? g_deg[i] : 0;
    int lane = t & 31, w = t >> 5;
    int s = v;
#pragma unroll
    for (int o = 1; o < 32; o <<= 1) {
        int u = __shfl_up_sync(0xffffffffu, s, o);
        if (lane >= o) s += u;
    }
    if (lane == 31) wsum[w] = s;
    __syncthreads();
    if (w == 0) {
        int ws = wsum[lane];
#pragma unroll
        for (int o = 1; o < 32; o <<= 1) {
            int u = __shfl_up_sync(0xffffffffu, ws, o);
            if (lane >= o) ws += u;
        }
        wsum[lane] = ws;
    }
    __syncthreads();
    int excl = s - v + (w > 0 ? wsum[w - 1] : 0);
    if (i < N_NODES) g_off[i] = excl;
    if (t == 1023) g_bsum[b] = excl + v;
}

__global__ void scan_tops_kernel()       // 1 block x 32
{
    int t = threadIdx.x;
    int v = (t < 20) ? g_bsum[t] : 0;
    int s = v;
#pragma unroll
    for (int o = 1; o < 32; o <<= 1) {
        int u = __shfl_up_sync(0xffffffffu, s, o);
        if (t >= o) s += u;
    }
    g_boff[t] = s - v;
}

__global__ void scan_add_kernel()        // 20 blocks x 1024
{
    int b = blockIdx.x, t = threadIdx.x;
    int i = b * 1024 + t;
    if (i < N_NODES) {
        int o = g_off[i] + g_boff[b];
        g_off[i] = o;
        g_cur[i] = o;
    }
    if (i == 0) g_off[N_NODES] = E_EDGES;
}

__global__ void scatter_kernel(const int* __restrict__ ei)
{
    int e = blockIdx.x * blockDim.x + threadIdx.x;
    if (e < E_EDGES) {
        int d = ei[E_EDGES + e];
        int pos = atomicAdd(&g_cur[d], 1);
        g_csr_src[pos] = ei[e];
    }
}

// ---------------- GATv2 attention + aggregation ----------------
__global__ void attn_kernel(const float* __restrict__ att, const float* __restrict__ bias)
{
    int warp = (blockIdx.x * blockDim.x + threadIdx.x) >> 5;
    int lane = threadIdx.x & 31;
    if (warp >= N_NODES) return;
    const int dst = warp;
    const int c0  = lane * 16;

    float xr_[16], at_[16];
    {
        const float4* p = (const float4*)&g_xr[dst * HC + c0];
        const float4* q = (const float4*)&att[c0];
#pragma unroll
        for (int k = 0; k < 4; k++) {
            float4 a = p[k]; float4 b = q[k];
            xr_[4*k+0] = a.x; xr_[4*k+1] = a.y; xr_[4*k+2] = a.z; xr_[4*k+3] = a.w;
            at_[4*k+0] = b.x; at_[4*k+1] = b.y; at_[4*k+2] = b.z; at_[4*k+3] = b.w;
        }
    }

    float m = -CUDART_INF_F;
    float s = 0.f;
    float acc[16];
#pragma unroll
    for (int j = 0; j < 16; j++) acc[j] = 0.f;

    const int beg = g_off[dst], end = g_off[dst + 1];
    for (int p = beg; p < end; p++) {
        int src = g_csr_src[p];
        float xl_[16];
        {
            const float4* q = (const float4*)&g_xl[src * HC + c0];
#pragma unroll
            for (int k = 0; k < 4; k++) {
                float4 a = q[k];
                xl_[4*k+0] = a.x; xl_[4*k+1] = a.y; xl_[4*k+2] = a.z; xl_[4*k+3] = a.w;
            }
        }
        float part = 0.f;
#pragma unroll
        for (int j = 0; j < 16; j++) {
            float v = xl_[j] + xr_[j];
            float lr = (v > 0.f) ? v : 0.2f * v;
            part = fmaf(lr, at_[j], part);
        }
        part += __shfl_xor_sync(0xffffffffu, part, 1);
        part += __shfl_xor_sync(0xffffffffu, part, 2);

        float mnew = fmaxf(m, part);
        float corr = __expf(m - mnew);
        float w    = __expf(part - mnew);
        s = s * corr + w;
#pragma unroll
        for (int j = 0; j < 16; j++) acc[j] = fmaf(acc[j], corr, w * xl_[j]);
        m = mnew;
    }

    float inv = 1.f / (s + 1e-16f);
    const float4* bq = (const float4*)&bias[c0];
#pragma unroll
    for (int k = 0; k < 4; k++) {
        float4 b = bq[k];
        float4 o;
        o.x = fmaf(acc[4*k+0], inv, b.x);
        o.y = fmaf(acc[4*k+1], inv, b.y);
        o.z = fmaf(acc[4*k+2], inv, b.z);
        o.w = fmaf(acc[4*k+3], inv, b.w);
        *(float4*)&g_out[dst * HC + c0 + 4*k] = o;
    }
}

// ---------------- BatchNorm stats (deterministic 2-stage) ----------------
__global__ void bn_partial_kernel()
{
    int c = threadIdx.x;
    float s = 0.f, ss = 0.f;
    for (int r = blockIdx.x; r < N_NODES; r += gridDim.x) {
        float v = g_out[r * HC + c];
        s += v;
        ss = fmaf(v, v, ss);
    }
    g_psum[blockIdx.x * HC + c] = s;
    g_psq [blockIdx.x * HC + c] = ss;
}

__global__ void bn_final_kernel(const float* __restrict__ gamma, const float* __restrict__ beta)
{
    int c = threadIdx.x;
    float s = 0.f, ss = 0.f;
    for (int b = 0; b < BN_BLOCKS; b++) {
        s  += g_psum[b * HC + c];
        ss += g_psq [b * HC + c];
    }
    float mu  = s / (float)N_NODES;
    float var = ss / (float)N_NODES - mu * mu;
    float sc  = gamma[c] * rsqrtf(var + 1e-5f);
    g_scale[c] = sc;
    g_shift[c] = beta[c] - mu * sc;
}

// ---------------- link scoring with fused BN+ReLU ----------------
__global__ void link_kernel(const int* __restrict__ eli, float* __restrict__ out)
{
    int w = (blockIdx.x * blockDim.x + threadIdx.x) >> 5;
    int lane = threadIdx.x & 31;
    if (w >= E_LABEL) return;
    int a = eli[w];
    int b = eli[E_LABEL + w];
    const int c0 = lane * 16;
    const float4* pa = (const float4*)&g_out[a * HC + c0];
    const float4* pb = (const float4*)&g_out[b * HC + c0];
    const float4* psc = (const float4*)&g_scale[c0];
    const float4* psh = (const float4*)&g_shift[c0];
    float p = 0.f;
#pragma unroll
    for (int k = 0; k < 4; k++) {
        float4 va = pa[k], vb = pb[k];
        float4 sc = psc[k], sh = psh[k];
        float ax = fmaxf(fmaf(va.x, sc.x, sh.x), 0.f);
        float ay = fmaxf(fmaf(va.y, sc.y, sh.y), 0.f);
        float az = fmaxf(fmaf(va.z, sc.z, sh.z), 0.f);
        float aw = fmaxf(fmaf(va.w, sc.w, sh.w), 0.f);
        float bx = fmaxf(fmaf(vb.x, sc.x, sh.x), 0.f);
        float by = fmaxf(fmaf(vb.y, sc.y, sh.y), 0.f);
        float bz = fmaxf(fmaf(vb.z, sc.z, sh.z), 0.f);
        float bw = fmaxf(fmaf(vb.w, sc.w, sh.w), 0.f);
        p = fmaf(ax, bx, p);
        p = fmaf(ay, by, p);
        p = fmaf(az, bz, p);
        p = fmaf(aw, bw, p);
    }
#pragma unroll
    for (int off = 16; off > 0; off >>= 1)
        p += __shfl_xor_sync(0xffffffffu, p, off);
    if (lane == 0) out[w] = p;
}

// ---------------- launch ----------------
static cudaStream_t s_side = nullptr;
static cudaEvent_t  s_evFork = nullptr, s_evJoin = nullptr;

extern "C" void kernel_launch(void* const* d_in, const int* in_sizes, int n_in,
                              void* d_out, int out_size)
{
    const float* x     = (const float*)d_in[0];
    const int*   ei    = (const int*)  d_in[1];
    const int*   eli   = (const int*)  d_in[2];
    const float* W_l   = (const float*)d_in[3];
    const float* W_r   = (const float*)d_in[4];
    const float* att   = (const float*)d_in[5];
    const float* bias  = (const float*)d_in[6];
    const float* gamma = (const float*)d_in[7];
    const float* beta  = (const float*)d_in[8];
    float* out = (float*)d_out;

    if (!s_side) {   // one-time handle creation (first call is outside graph capture)
        cudaStreamCreateWithFlags(&s_side, cudaStreamNonBlocking);
        cudaEventCreateWithFlags(&s_evFork, cudaEventDisableTiming);
        cudaEventCreateWithFlags(&s_evJoin, cudaEventDisableTiming);
    }

    // main stream: conversions (conv_w also zeroes g_deg)
    conv_x_kernel<<<(N_PAD * IN_CH / 4 + 255) / 256, 256>>>(x);
    {
        dim3 g(IN_CH * HC / 256, 2);
        conv_w_kernel<<<g, 256>>>(W_l, W_r);
    }

    // fork: CSR build runs on side stream concurrently with the GEMM
    cudaEventRecord(s_evFork, 0);
    cudaStreamWaitEvent(s_side, s_evFork, 0);
    hist_kernel<<<(E_EDGES + 255) / 256, 256, 0, s_side>>>(ei);
    scan_blocks_kernel<<<20, 1024, 0, s_side>>>();
    scan_tops_kernel<<<1, 32, 0, s_side>>>();
    scan_add_kernel<<<20, 1024, 0, s_side>>>();
    scatter_kernel<<<(E_EDGES + 255) / 256, 256, 0, s_side>>>(ei);
    cudaEventRecord(s_evJoin, s_side);

    // main stream: HMMA split-bf16 GEMMs
    {
        dim3 g(HC / 128, N_PAD / 128, 2);
        gemm_tc_kernel<<<g, 256>>>();
    }

    // join, then attention + aggregation
    cudaStreamWaitEvent(0, s_evJoin, 0);
    attn_kernel<<<(N_NODES * 32) / 256, 256>>>(att, bias);

    // batch norm stats
    bn_partial_kernel<<<BN_BLOCKS, HC>>>();
    bn_final_kernel<<<1, HC>>>(gamma, beta);

    // link scoring with fused BN + ReLU
    link_kernel<<<(E_LABEL * 32) / 256, 256>>>(eli, out);
}

// round 5
// speedup vs baseline: 1.0744x; 1.0744x over previous
#include <cuda_runtime.h>
#include <cuda_bf16.h>
#include <math_constants.h>
#include <cstdint>

// Problem constants
#define N_NODES 20000
#define N_PAD   20096          // 157 * 128
#define IN_CH   512
#define HC      512
#define HEADS   8
#define CH      64
#define E_EDGES 320000
#define E_LABEL 100000
#define BN_BLOCKS 128

// ---------------- scratch ----------------
__device__ __nv_bfloat16 g_xhi[N_PAD * IN_CH];
__device__ __nv_bfloat16 g_xlo[N_PAD * IN_CH];
__device__ __nv_bfloat16 g_wthi[2][IN_CH * HC];
__device__ __nv_bfloat16 g_wtlo[2][IN_CH * HC];
__device__ float g_xl[N_PAD * HC];
__device__ float g_xr[N_PAD * HC];
__device__ float g_out[N_NODES * HC];
__device__ int   g_deg[N_NODES + 1];
__device__ int   g_off[N_NODES + 1];
__device__ int   g_cur[N_NODES];
__device__ int   g_csr_src[E_EDGES];
__device__ int   g_bsum[32];
__device__ float g_psum[BN_BLOCKS * HC];
__device__ float g_psq [BN_BLOCKS * HC];
__device__ float g_scale[HC];
__device__ float g_shift[HC];

// ---------------- helpers ----------------
__device__ __forceinline__ uint32_t smem_u32(const void* p) {
    uint32_t a;
    asm("{ .reg .u64 t; cvta.to.shared.u64 t, %1; cvt.u32.u64 %0, t; }" : "=r"(a) : "l"(p));
    return a;
}
__device__ __forceinline__ void cp_async16(uint32_t sa, const void* ga) {
    asm volatile("cp.async.cg.shared.global [%0], [%1], 16;" :: "r"(sa), "l"(ga) : "memory");
}
__device__ __forceinline__ void cp_commit() {
    asm volatile("cp.async.commit_group;" ::: "memory");
}
__device__ __forceinline__ void cp_wait1() {
    asm volatile("cp.async.wait_group 1;" ::: "memory");
}
__device__ __forceinline__ void cp_wait0() {
    asm volatile("cp.async.wait_group 0;" ::: "memory");
}
__device__ __forceinline__ void ldm_x4(uint32_t* r, uint32_t addr) {
    asm volatile("ldmatrix.sync.aligned.m8n8.x4.shared.b16 {%0,%1,%2,%3}, [%4];"
                 : "=r"(r[0]), "=r"(r[1]), "=r"(r[2]), "=r"(r[3]) : "r"(addr));
}
__device__ __forceinline__ void mma16816(float* d, const uint32_t* a, const uint32_t* b) {
    asm volatile("mma.sync.aligned.m16n8k16.row.col.f32.bf16.bf16.f32 "
                 "{%0,%1,%2,%3}, {%4,%5,%6,%7}, {%8,%9}, {%0,%1,%2,%3};"
                 : "+f"(d[0]), "+f"(d[1]), "+f"(d[2]), "+f"(d[3])
                 : "r"(a[0]), "r"(a[1]), "r"(a[2]), "r"(a[3]), "r"(b[0]), "r"(b[1]));
}

// ---------------- fused conversion: x hi/lo split + W transpose/split + g_deg zero ----------------
#define CONVX_BLOCKS (N_PAD * IN_CH / 4 / 256)      // 10048
#define CONVW_BLOCKS (2 * IN_CH * HC / 256)         // 2048

__global__ void conv_fused_kernel(const float* __restrict__ x,
                                  const float* __restrict__ Wl,
                                  const float* __restrict__ Wr)
{
    int bid = blockIdx.x;
    if (bid < CONVX_BLOCKS) {
        int i4 = bid * 256 + threadIdx.x;
        if (i4 <= N_NODES) g_deg[i4] = 0;
        int i = i4 * 4;
        int row = i >> 9;
        float4 v = (row < N_NODES) ? *(const float4*)(x + i) : make_float4(0.f, 0.f, 0.f, 0.f);
        float a[4] = {v.x, v.y, v.z, v.w};
        __nv_bfloat16 h0 = __float2bfloat16(a[0]);
        __nv_bfloat16 h1 = __float2bfloat16(a[1]);
        __nv_bfloat16 h2 = __float2bfloat16(a[2]);
        __nv_bfloat16 h3 = __float2bfloat16(a[3]);
        __nv_bfloat16 l0 = __float2bfloat16(a[0] - __bfloat162float(h0));
        __nv_bfloat16 l1 = __float2bfloat16(a[1] - __bfloat162float(h1));
        __nv_bfloat16 l2 = __float2bfloat16(a[2] - __bfloat162float(h2));
        __nv_bfloat16 l3 = __float2bfloat16(a[3] - __bfloat162float(h3));
        uint32_t hi01 = ((uint32_t)__bfloat16_as_ushort(h1) << 16) | __bfloat16_as_ushort(h0);
        uint32_t hi23 = ((uint32_t)__bfloat16_as_ushort(h3) << 16) | __bfloat16_as_ushort(h2);
        uint32_t lo01 = ((uint32_t)__bfloat16_as_ushort(l1) << 16) | __bfloat16_as_ushort(l0);
        uint32_t lo23 = ((uint32_t)__bfloat16_as_ushort(l3) << 16) | __bfloat16_as_ushort(l2);
        *(uint2*)((char*)g_xhi + i * 2) = make_uint2(hi01, hi23);
        *(uint2*)((char*)g_xlo + i * 2) = make_uint2(lo01, lo23);
    } else {
        int j = (bid - CONVX_BLOCKS) * 256 + threadIdx.x;   // 0 .. 2*512*512-1
        int mat = j >> 18;
        int i = j & 0x3FFFF;                                // n*512 + k
        const float* W = mat ? Wr : Wl;
        int n = i >> 9, k = i & 511;
        float v = W[k * HC + n];
        __nv_bfloat16 h = __float2bfloat16(v);
        g_wthi[mat][i] = h;
        g_wtlo[mat][i] = __float2bfloat16(v - __bfloat162float(h));
    }
}

// ---------------- HMMA split-bf16 GEMM ----------------
// 16 k-chunks; per chunk load Ah/Al/Bh/Bl tiles and do all 3 MMA combos.
#define SMS 80                      // smem row stride bytes (64B row + 16B pad)
#define TILE_BYTES (128 * SMS)      // 10240
#define STAGE_BYTES (4 * TILE_BYTES)
#define GSMEM_TOTAL (2 * STAGE_BYTES)   // 81920

__global__ void __launch_bounds__(256, 2) gemm_tc_kernel()
{
    extern __shared__ __align__(16) char smem[];

    const int tid  = threadIdx.x;
    const int wid  = tid >> 5;
    const int lane = tid & 31;
    const int wm   = wid & 1;
    const int wn   = wid >> 1;

    const int m0  = blockIdx.y * 128;
    const int n0  = blockIdx.x * 128;
    const int mat = blockIdx.z;

    const __nv_bfloat16* Ah = g_xhi + (size_t)m0 * IN_CH;
    const __nv_bfloat16* Al = g_xlo + (size_t)m0 * IN_CH;
    const __nv_bfloat16* Bh = g_wthi[mat] + (size_t)n0 * IN_CH;
    const __nv_bfloat16* Bl = g_wtlo[mat] + (size_t)n0 * IN_CH;
    float* C = mat ? g_xr : g_xl;

    const uint32_t sb = smem_u32(smem);
    // stage s, tile t (0=Ah,1=Al,2=Bh,3=Bl)
    const int r0 = tid >> 2;          // 0..63
    const int c0 = tid & 3;           // 16B chunk

    float acc[4][4][4];
#pragma unroll
    for (int i = 0; i < 4; i++)
#pragma unroll
        for (int j = 0; j < 4; j++)
#pragma unroll
            for (int q = 0; q < 4; q++) acc[i][j][q] = 0.f;

    auto issue = [&](int kc, int stg) {
        const uint32_t base = sb + stg * STAGE_BYTES;
        const int kel = kc * 32 + c0 * 8;
#pragma unroll
        for (int j = 0; j < 2; j++) {
            int row = r0 + j * 64;
            uint32_t so = row * SMS + c0 * 16;
            size_t  go = (size_t)row * IN_CH + kel;
            cp_async16(base + 0 * TILE_BYTES + so, Ah + go);
            cp_async16(base + 1 * TILE_BYTES + so, Al + go);
            cp_async16(base + 2 * TILE_BYTES + so, Bh + go);
            cp_async16(base + 3 * TILE_BYTES + so, Bl + go);
        }
    };

    issue(0, 0); cp_commit();

    for (int kc = 0; kc < 16; kc++) {
        if (kc + 1 < 16) { issue(kc + 1, (kc + 1) & 1); cp_commit(); cp_wait1(); }
        else             { cp_wait0(); }
        __syncthreads();

        const uint32_t base = sb + (kc & 1) * STAGE_BYTES;
#pragma unroll
        for (int ks = 0; ks < 2; ks++) {
            const int kb = ks * 32;
            uint32_t ah[4][4], al[4][4];
#pragma unroll
            for (int mt = 0; mt < 4; mt++) {
                int row = wm * 64 + mt * 16 + ((lane >> 3) & 1) * 8 + (lane & 7);
                uint32_t off = row * SMS + kb + ((lane >> 4) & 1) * 16;
                ldm_x4(ah[mt], base + 0 * TILE_BYTES + off);
                ldm_x4(al[mt], base + 1 * TILE_BYTES + off);
            }
            uint32_t bh[4][2], bl[4][2];
#pragma unroll
            for (int nh = 0; nh < 2; nh++) {
                int row = wn * 32 + nh * 16 + (lane >> 4) * 8 + (lane & 7);
                uint32_t off = row * SMS + kb + ((lane >> 3) & 1) * 16;
                uint32_t t[4];
                ldm_x4(t, base + 2 * TILE_BYTES + off);
                bh[nh * 2 + 0][0] = t[0]; bh[nh * 2 + 0][1] = t[1];
                bh[nh * 2 + 1][0] = t[2]; bh[nh * 2 + 1][1] = t[3];
                ldm_x4(t, base + 3 * TILE_BYTES + off);
                bl[nh * 2 + 0][0] = t[0]; bl[nh * 2 + 0][1] = t[1];
                bl[nh * 2 + 1][0] = t[2]; bl[nh * 2 + 1][1] = t[3];
            }
#pragma unroll
            for (int mt = 0; mt < 4; mt++)
#pragma unroll
                for (int nt = 0; nt < 4; nt++) {
                    mma16816(acc[mt][nt], ah[mt], bh[nt]);
                    mma16816(acc[mt][nt], ah[mt], bl[nt]);
                    mma16816(acc[mt][nt], al[mt], bh[nt]);
                }
        }
        __syncthreads();
    }

    const int g = lane >> 2;
    const int q = lane & 3;
#pragma unroll
    for (int mt = 0; mt < 4; mt++) {
#pragma unroll
        for (int nt = 0; nt < 4; nt++) {
            int row = m0 + wm * 64 + mt * 16 + g;
            int col = n0 + wn * 32 + nt * 8 + q * 2;
            *(float2*)&C[(size_t)row * HC + col] =
                make_float2(acc[mt][nt][0], acc[mt][nt][1]);
            *(float2*)&C[(size_t)(row + 8) * HC + col] =
                make_float2(acc[mt][nt][2], acc[mt][nt][3]);
        }
    }
}

// ---------------- CSR build ----------------
__global__ void hist_kernel(const int* __restrict__ ei)
{
    int e = blockIdx.x * blockDim.x + threadIdx.x;
    if (e < E_EDGES) atomicAdd(&g_deg[ei[E_EDGES + e]], 1);
}

__global__ void scan_blocks_kernel()     // 20 blocks x 1024
{
    __shared__ int wsum[32];
    int b = blockIdx.x, t = threadIdx.x;
    int i = b * 1024 + t;
    int v = (i < N_NODES) ? g_deg[i] : 0;
    int lane = t & 31, w = t >> 5;
    int s = v;
#pragma unroll
    for (int o = 1; o < 32; o <<= 1) {
        int u = __shfl_up_sync(0xffffffffu, s, o);
        if (lane >= o) s += u;
    }
    if (lane == 31) wsum[w] = s;
    __syncthreads();
    if (w == 0) {
        int ws = wsum[lane];
#pragma unroll
        for (int o = 1; o < 32; o <<= 1) {
            int u = __shfl_up_sync(0xffffffffu, ws, o);
            if (lane >= o) ws += u;
        }
        wsum[lane] = ws;
    }
    __syncthreads();
    int excl = s - v + (w > 0 ? wsum[w - 1] : 0);
    if (i < N_NODES) g_off[i] = excl;
    if (t == 1023) g_bsum[b] = excl + v;
}

// folds the 20-entry block-sum prefix into each block (20 serial adds, trivial)
__global__ void scan_add_kernel()        // 20 blocks x 1024
{
    __shared__ int boff;
    int b = blockIdx.x, t = threadIdx.x;
    if (t == 0) {
        int s = 0;
        for (int j = 0; j < b; j++) s += g_bsum[j];
        boff = s;
    }
    __syncthreads();
    int i = b * 1024 + t;
    if (i < N_NODES) {
        int o = g_off[i] + boff;
        g_off[i] = o;
        g_cur[i] = o;
    }
    if (i == 0) g_off[N_NODES] = E_EDGES;
}

__global__ void scatter_kernel(const int* __restrict__ ei)
{
    int e = blockIdx.x * blockDim.x + threadIdx.x;
    if (e < E_EDGES) {
        int d = ei[E_EDGES + e];
        int pos = atomicAdd(&g_cur[d], 1);
        g_csr_src[pos] = ei[e];
    }
}

// ---------------- GATv2 attention + aggregation ----------------
__global__ void attn_kernel(const float* __restrict__ att, const float* __restrict__ bias)
{
    int warp = (blockIdx.x * blockDim.x + threadIdx.x) >> 5;
    int lane = threadIdx.x & 31;
    if (warp >= N_NODES) return;
    const int dst = warp;
    const int c0  = lane * 16;

    float xr_[16], at_[16];
    {
        const float4* p = (const float4*)&g_xr[dst * HC + c0];
        const float4* q = (const float4*)&att[c0];
#pragma unroll
        for (int k = 0; k < 4; k++) {
            float4 a = p[k]; float4 b = q[k];
            xr_[4*k+0] = a.x; xr_[4*k+1] = a.y; xr_[4*k+2] = a.z; xr_[4*k+3] = a.w;
            at_[4*k+0] = b.x; at_[4*k+1] = b.y; at_[4*k+2] = b.z; at_[4*k+3] = b.w;
        }
    }

    float m = -CUDART_INF_F;
    float s = 0.f;
    float acc[16];
#pragma unroll
    for (int j = 0; j < 16; j++) acc[j] = 0.f;

    const int beg = g_off[dst], end = g_off[dst + 1];
    for (int p = beg; p < end; p++) {
        int src = g_csr_src[p];
        float xl_[16];
        {
            const float4* q = (const float4*)&g_xl[src * HC + c0];
#pragma unroll
            for (int k = 0; k < 4; k++) {
                float4 a = q[k];
                xl_[4*k+0] = a.x; xl_[4*k+1] = a.y; xl_[4*k+2] = a.z; xl_[4*k+3] = a.w;
            }
        }
        float part = 0.f;
#pragma unroll
        for (int j = 0; j < 16; j++) {
            float v = xl_[j] + xr_[j];
            float lr = (v > 0.f) ? v : 0.2f * v;
            part = fmaf(lr, at_[j], part);
        }
        part += __shfl_xor_sync(0xffffffffu, part, 1);
        part += __shfl_xor_sync(0xffffffffu, part, 2);

        float mnew = fmaxf(m, part);
        float corr = __expf(m - mnew);
        float w    = __expf(part - mnew);
        s = s * corr + w;
#pragma unroll
        for (int j = 0; j < 16; j++) acc[j] = fmaf(acc[j], corr, w * xl_[j]);
        m = mnew;
    }

    float inv = 1.f / (s + 1e-16f);
    const float4* bq = (const float4*)&bias[c0];
#pragma unroll
    for (int k = 0; k < 4; k++) {
        float4 b = bq[k];
        float4 o;
        o.x = fmaf(acc[4*k+0], inv, b.x);
        o.y = fmaf(acc[4*k+1], inv, b.y);
        o.z = fmaf(acc[4*k+2], inv, b.z);
        o.w = fmaf(acc[4*k+3], inv, b.w);
        *(float4*)&g_out[dst * HC + c0 + 4*k] = o;
    }
}

// ---------------- BatchNorm stats (deterministic 2-stage) ----------------
__global__ void bn_partial_kernel()
{
    int c = threadIdx.x;
    float s = 0.f, ss = 0.f;
    for (int r = blockIdx.x; r < N_NODES; r += gridDim.x) {
        float v = g_out[r * HC + c];
        s += v;
        ss = fmaf(v, v, ss);
    }
    g_psum[blockIdx.x * HC + c] = s;
    g_psq [blockIdx.x * HC + c] = ss;
}

__global__ void bn_final_kernel(const float* __restrict__ gamma, const float* __restrict__ beta)
{
    int c = threadIdx.x;
    float s = 0.f, ss = 0.f;
    for (int b = 0; b < BN_BLOCKS; b++) {
        s  += g_psum[b * HC + c];
        ss += g_psq [b * HC + c];
    }
    float mu  = s / (float)N_NODES;
    float var = ss / (float)N_NODES - mu * mu;
    float sc  = gamma[c] * rsqrtf(var + 1e-5f);
    g_scale[c] = sc;
    g_shift[c] = beta[c] - mu * sc;
}

// ---------------- link scoring with fused BN+ReLU ----------------
__global__ void link_kernel(const int* __restrict__ eli, float* __restrict__ out)
{
    int w = (blockIdx.x * blockDim.x + threadIdx.x) >> 5;
    int lane = threadIdx.x & 31;
    if (w >= E_LABEL) return;
    int a = eli[w];
    int b = eli[E_LABEL + w];
    const int c0 = lane * 16;
    const float4* pa = (const float4*)&g_out[a * HC + c0];
    const float4* pb = (const float4*)&g_out[b * HC + c0];
    const float4* psc = (const float4*)&g_scale[c0];
    const float4* psh = (const float4*)&g_shift[c0];
    float p = 0.f;
#pragma unroll
    for (int k = 0; k < 4; k++) {
        float4 va = pa[k], vb = pb[k];
        float4 sc = psc[k], sh = psh[k];
        float ax = fmaxf(fmaf(va.x, sc.x, sh.x), 0.f);
        float ay = fmaxf(fmaf(va.y, sc.y, sh.y), 0.f);
        float az = fmaxf(fmaf(va.z, sc.z, sh.z), 0.f);
        float aw = fmaxf(fmaf(va.w, sc.w, sh.w), 0.f);
        float bx = fmaxf(fmaf(vb.x, sc.x, sh.x), 0.f);
        float by = fmaxf(fmaf(vb.y, sc.y, sh.y), 0.f);
        float bz = fmaxf(fmaf(vb.z, sc.z, sh.z), 0.f);
        float bw = fmaxf(fmaf(vb.w, sc.w, sh.w), 0.f);
        p = fmaf(ax, bx, p);
        p = fmaf(ay, by, p);
        p = fmaf(az, bz, p);
        p = fmaf(aw, bw, p);
    }
#pragma unroll
    for (int off = 16; off > 0; off >>= 1)
        p += __shfl_xor_sync(0xffffffffu, p, off);
    if (lane == 0) out[w] = p;
}

// ---------------- launch ----------------
extern "C" void kernel_launch(void* const* d_in, const int* in_sizes, int n_in,
                              void* d_out, int out_size)
{
    const float* x     = (const float*)d_in[0];
    const int*   ei    = (const int*)  d_in[1];
    const int*   eli   = (const int*)  d_in[2];
    const float* W_l   = (const float*)d_in[3];
    const float* W_r   = (const float*)d_in[4];
    const float* att   = (const float*)d_in[5];
    const float* bias  = (const float*)d_in[6];
    const float* gamma = (const float*)d_in[7];
    const float* beta  = (const float*)d_in[8];
    float* out = (float*)d_out;

    static bool s_init = false;
    if (!s_init) {
        cudaFuncSetAttribute(gemm_tc_kernel,
                             cudaFuncAttributeMaxDynamicSharedMemorySize, GSMEM_TOTAL);
        s_init = true;
    }

    // fused conversions (also zeroes g_deg)
    conv_fused_kernel<<<CONVX_BLOCKS + CONVW_BLOCKS, 256>>>(x, W_l, W_r);

    // CSR build
    hist_kernel<<<(E_EDGES + 255) / 256, 256>>>(ei);
    scan_blocks_kernel<<<20, 1024>>>();
    scan_add_kernel<<<20, 1024>>>();
    scatter_kernel<<<(E_EDGES + 255) / 256, 256>>>(ei);

    // HMMA split-bf16 GEMMs
    {
        dim3 g(HC / 128, N_PAD / 128, 2);
        gemm_tc_kernel<<<g, 256, GSMEM_TOTAL>>>();
    }

    // attention + aggregation
    attn_kernel<<<(N_NODES * 32) / 256, 256>>>(att, bias);

    // batch norm stats
    bn_partial_kernel<<<BN_BLOCKS, HC>>>();
    bn_final_kernel<<<1, HC>>>(gamma, beta);

    // link scoring with fused BN + ReLU
    link_kernel<<<(E_LABEL * 32) / 256, 256>>>(eli, out);
}